// round 13
// baseline (speedup 1.0000x reference)
#include <cuda_runtime.h>
#include <cuda_bf16.h>
#include <math.h>
#include <stdint.h>

#define N 8192
#define D 512
#define BLK 128                    // block size (square)
#define NBLK (N / BLK)             // 64 row/col blocks
#define NJOBS (NBLK * (NBLK + 1) / 2)   // 2080 upper-triangle tile jobs
#define GRID 148
#define KC 64                      // K chunk
#define KTOP 5
#define NTHREADS 512

// Scratch (no cudaMalloc allowed)
static __device__ __nv_bfloat16 g_xnb[(size_t)N * D];        // 8 MB normalized rows
static __device__ float g_part[(size_t)N * NBLK * KTOP];     // 10.5 MB partial top-5
static __device__ float g_logrho[N];

// SMEM: A panel 128 KB + 2x 16 KB B buffers + C tile 128x129 fp32 (66 KB)
#define SA_BYTES (128 * 1024)
#define SB_BYTES (16 * 1024)
#define SB0_OFF  SA_BYTES                  // 131072
#define SC_OFF   (SB0_OFF + 2 * SB_BYTES)  // 163840
#define SMEM_TOTAL (SC_OFF + 128 * 129 * 4)  // 229888

// ---- PTX helpers ------------------------------------------------------------
__device__ __forceinline__ uint32_t smem_u32(const void* p) {
    uint32_t a;
    asm("{ .reg .u64 t; cvta.to.shared.u64 t, %1; cvt.u32.u64 %0, t; }" : "=r"(a) : "l"(p));
    return a;
}
__device__ __forceinline__ void ldsm_x4(uint32_t* r, uint32_t addr) {
    asm volatile("ldmatrix.sync.aligned.m8n8.x4.shared.b16 {%0,%1,%2,%3}, [%4];"
                 : "=r"(r[0]), "=r"(r[1]), "=r"(r[2]), "=r"(r[3]) : "r"(addr));
}
__device__ __forceinline__ void mma_bf16(float* d, const uint32_t* a,
                                         uint32_t b0, uint32_t b1) {
    asm volatile(
        "mma.sync.aligned.m16n8k16.row.col.f32.bf16.bf16.f32 "
        "{%0,%1,%2,%3}, {%4,%5,%6,%7}, {%8,%9}, {%0,%1,%2,%3};"
        : "+f"(d[0]), "+f"(d[1]), "+f"(d[2]), "+f"(d[3])
        : "r"(a[0]), "r"(a[1]), "r"(a[2]), "r"(a[3]), "r"(b0), "r"(b1));
}
__device__ __forceinline__ void cp16(uint32_t dst, const void* src) {
    asm volatile("cp.async.cg.shared.global [%0], [%1], 16;" :: "r"(dst), "l"(src));
}
__device__ __forceinline__ void cp_commit() {
    asm volatile("cp.async.commit_group;" ::: "memory");
}
__device__ __forceinline__ void cp_wait1() {
    asm volatile("cp.async.wait_group 1;" ::: "memory");
}
__device__ __forceinline__ void cp_wait0() {
    asm volatile("cp.async.wait_group 0;" ::: "memory");
}
// insert v into ascending 5-list (t0 = smallest kept)
__device__ __forceinline__ void ins5(float v, float& t0, float& t1, float& t2,
                                     float& t3, float& t4) {
    if (v > t0) {
        t0 = v;
        if (t0 > t1) { float tm = t0; t0 = t1; t1 = tm;
          if (t1 > t2) { tm = t1; t1 = t2; t2 = tm;
            if (t2 > t3) { tm = t2; t2 = t3; t3 = tm;
              if (t3 > t4) { tm = t3; t3 = t4; t4 = tm; } } } }
    }
}
// base(I) = number of jobs before row-stripe I in row-major triangle order
__device__ __forceinline__ int tri_base(int i) { return i * NBLK - (i * (i - 1)) / 2; }
__device__ __forceinline__ void job_ij(int t, int& I, int& J) {
    int i = (int)(64.5f - sqrtf(64.5f * 64.5f - 2.0f * (float)t));
    if (i < 0) i = 0;
    while (i + 1 < NBLK && tri_base(i + 1) <= t) i++;
    while (i > 0 && tri_base(i) > t) i--;
    I = i;
    J = i + (t - tri_base(i));
}

// ---------------------------------------------------------------------------
// Kernel 1: row-normalize + cast to bf16. One block (128 threads) per row.
// ---------------------------------------------------------------------------
__global__ void knorm(const float* __restrict__ x, __nv_bfloat16* __restrict__ xnb) {
    int row = blockIdx.x;
    int t = threadIdx.x;
    float4 v = ((const float4*)(x + (size_t)row * D))[t];
    float s = v.x * v.x + v.y * v.y + v.z * v.z + v.w * v.w;
    #pragma unroll
    for (int o = 16; o; o >>= 1) s += __shfl_xor_sync(0xffffffffu, s, o);
    __shared__ float ws[4];
    if ((t & 31) == 0) ws[t >> 5] = s;
    __syncthreads();
    float inv = rsqrtf(ws[0] + ws[1] + ws[2] + ws[3]);
    __nv_bfloat162 p0 = __floats2bfloat162_rn(v.x * inv, v.y * inv);
    __nv_bfloat162 p1 = __floats2bfloat162_rn(v.z * inv, v.w * inv);
    uint2 o2;
    o2.x = *(uint32_t*)&p0;
    o2.y = *(uint32_t*)&p1;
    ((uint2*)(xnb + (size_t)row * D))[t] = o2;
}

// ---------------------------------------------------------------------------
// Prefetch one 128x64 bf16 K-chunk of block Jblk into B buffer `buf`.
// ---------------------------------------------------------------------------
__device__ __forceinline__ void prefetch_B(uint32_t sb, const __nv_bfloat16* xnb,
                                           int Jblk, int kb, int buf, int tid) {
    const uint32_t dstb = sb + SB0_OFF + (uint32_t)buf * SB_BYTES;
    const __nv_bfloat16* src = xnb + (size_t)Jblk * BLK * D + kb * KC;
    #pragma unroll
    for (int it = 0; it < 2; it++) {
        int idx = tid + it * NTHREADS;       // 0..1023 16B chunks
        int n = idx >> 3, c16 = idx & 7;
        uint32_t off = (uint32_t)n * 128 + (uint32_t)c16 * 16;
        uint32_t sw = off ^ ((uint32_t)(n & 7) << 4);
        cp16(dstb + sw, src + (size_t)n * D + c16 * 8);
    }
    cp_commit();
}

// ---------------------------------------------------------------------------
// Kernel 2: symmetric-schedule bf16 GEMM + per-tile row/col top-5.
// 148 CTAs, each owning a contiguous range of the 2080 upper-triangle jobs.
// 512 threads = 16 warps (4M x 4N), warp tile 32x32. A(I) panel SMEM-resident,
// B(J) streamed in double-buffered cp.async chunks. Epilogue stages C in
// padded SMEM and scans both rows (block I) and cols (block J, symmetry).
// ---------------------------------------------------------------------------
__global__ void __launch_bounds__(NTHREADS, 1)
gemm_topk(const __nv_bfloat16* __restrict__ xnb, float* __restrict__ gpart) {
    extern __shared__ char smem[];
    const uint32_t sb = smem_u32(smem);
    float* Csm = (float*)(smem + SC_OFF);
    const int tid = threadIdx.x;
    const int wid = tid >> 5, lane = tid & 31;
    const int wm = wid & 3;          // 4 M-groups of 32 rows
    const int wn = wid >> 2;         // 4 N-groups of 32 cols

    const int q = lane >> 3;
    const int lr = lane & 7;
    const uint32_t swz = (uint32_t)lr << 4;

    const int j0 = (blockIdx.x * NJOBS) / GRID;
    const int j1 = ((blockIdx.x + 1) * NJOBS) / GRID;
    const int nc = (j1 - j0) * 8;

    // ldmatrix base offsets
    uint32_t aoff[2], boff[2];
    #pragma unroll
    for (int mt = 0; mt < 2; mt++) {
        int arow = wm * 32 + mt * 16 + (q & 1) * 8 + lr;
        aoff[mt] = (uint32_t)arow * 1024 + (uint32_t)(q >> 1) * 16;
    }
    #pragma unroll
    for (int np = 0; np < 2; np++) {
        int bn = wn * 32 + np * 16 + (q & 1) * 8 + lr;
        boff[np] = (uint32_t)bn * 128 + (uint32_t)(q >> 1) * 16;
    }

    int I, J;
    job_ij(j0, I, J);
    int curI = -1;

    // prefetch chunk 0 of first job
    prefetch_B(sb, xnb, J, 0, 0, tid);

    for (int t = j0; t < j1; t++) {
        job_ij(t, I, J);

        if (I != curI) {
            // load resident A panel (block I): 128 rows x 512 bf16, swizzled
            #pragma unroll
            for (int it = 0; it < 16; it++) {
                int idx = tid + it * NTHREADS;
                int r = idx >> 6, c16 = idx & 63;
                uint32_t off = (uint32_t)r * 1024 + (uint32_t)c16 * 16;
                uint32_t sw = off ^ ((uint32_t)(r & 7) << 4);
                *(uint4*)(smem + sw) =
                    *(const uint4*)(xnb + (size_t)(I * BLK + r) * D + c16 * 8);
            }
            curI = I;
        }

        float acc[2][4][4];
        #pragma unroll
        for (int mt = 0; mt < 2; mt++)
            #pragma unroll
            for (int nt = 0; nt < 4; nt++)
                #pragma unroll
                for (int j = 0; j < 4; j++) acc[mt][nt][j] = 0.f;

        #pragma unroll
        for (int kb = 0; kb < 8; kb++) {
            const int g = (t - j0) * 8 + kb;
            if (g + 1 < nc) {
                int t2 = j0 + ((g + 1) >> 3);
                int I2, J2;
                job_ij(t2, I2, J2);
                prefetch_B(sb, xnb, J2, (g + 1) & 7, (g + 1) & 1, tid);
                cp_wait1();
            } else {
                cp_wait0();
            }
            __syncthreads();   // chunk g arrived; A panel (if reloaded) visible

            const uint32_t bbase = sb + SB0_OFF + (uint32_t)(g & 1) * SB_BYTES;

            #pragma unroll
            for (int k16 = 0; k16 < 4; k16++) {
                uint32_t a[2][4], b[2][4];
                #pragma unroll
                for (int mt = 0; mt < 2; mt++)
                    ldsm_x4(a[mt], sb + ((aoff[mt] + kb * 128 + k16 * 32) ^ swz));
                #pragma unroll
                for (int np = 0; np < 2; np++)
                    ldsm_x4(b[np], bbase + ((boff[np] + k16 * 32) ^ swz));
                #pragma unroll
                for (int mt = 0; mt < 2; mt++)
                    #pragma unroll
                    for (int nt = 0; nt < 4; nt++) {
                        const int np = nt >> 1, w = nt & 1;
                        mma_bf16(acc[mt][nt], a[mt], b[np][w], b[np][w + 2]);
                    }
            }
            __syncthreads();   // buffer reads done before its refill next iter
        }

        // ---- epilogue: stage C in padded SMEM, scan rows and cols ----
        #pragma unroll
        for (int mt = 0; mt < 2; mt++)
            #pragma unroll
            for (int nt = 0; nt < 4; nt++)
                #pragma unroll
                for (int half = 0; half < 2; half++)
                    #pragma unroll
                    for (int j = 0; j < 2; j++) {
                        int r = wm * 32 + mt * 16 + half * 8 + (lane >> 2);
                        int c = wn * 32 + nt * 8 + 2 * (lane & 3) + j;
                        Csm[r * 129 + c] = acc[mt][nt][half * 2 + j];
                    }
        __syncthreads();

        if (tid < 128) {
            // row scan: row I*128+tid vs cols of block J -> slot J
            const bool diag = (I == J);
            float t0 = -2.f, t1 = -2.f, t2 = -2.f, t3 = -2.f, t4 = -2.f;
            const float* rowp = Csm + tid * 129;
            #pragma unroll 8
            for (int c = 0; c < 128; c++) {
                float v = rowp[c];
                if (!(diag && c == tid)) ins5(v, t0, t1, t2, t3, t4);
            }
            float* dst = gpart + ((size_t)(I * BLK + tid) * NBLK + J) * KTOP;
            dst[0] = t0; dst[1] = t1; dst[2] = t2; dst[3] = t3; dst[4] = t4;
        } else if (tid < 256 && I != J) {
            // col scan: row J*128+c vs cols of block I (symmetry) -> slot I
            const int c = tid - 128;
            float t0 = -2.f, t1 = -2.f, t2 = -2.f, t3 = -2.f, t4 = -2.f;
            #pragma unroll 8
            for (int r = 0; r < 128; r++)
                ins5(Csm[r * 129 + c], t0, t1, t2, t3, t4);
            float* dst = gpart + ((size_t)(J * BLK + c) * NBLK + I) * KTOP;
            dst[0] = t0; dst[1] = t1; dst[2] = t2; dst[3] = t3; dst[4] = t4;
        }
        __syncthreads();   // Csm consumed before next job overwrites it
    }
}

// ---------------------------------------------------------------------------
// Kernel 3: merge 64 partial top-5 lists per row, compute log(mean_rho+eps).
// ---------------------------------------------------------------------------
__global__ void kfinal(const float* __restrict__ gpart, float* __restrict__ lr) {
    int row = blockIdx.x * 256 + threadIdx.x;
    const float4* p = (const float4*)(gpart + (size_t)row * NBLK * KTOP);
    float t0 = -2.f, t1 = -2.f, t2 = -2.f, t3 = -2.f, t4 = -2.f;
    #pragma unroll 8
    for (int i = 0; i < NBLK * KTOP / 4; i++) {
        float4 v = p[i];
        ins5(v.x, t0, t1, t2, t3, t4);
        ins5(v.y, t0, t1, t2, t3, t4);
        ins5(v.z, t0, t1, t2, t3, t4);
        ins5(v.w, t0, t1, t2, t3, t4);
    }
    float sum = sqrtf(fmaxf(2.f - 2.f * t0, 0.f))
              + sqrtf(fmaxf(2.f - 2.f * t1, 0.f))
              + sqrtf(fmaxf(2.f - 2.f * t2, 0.f))
              + sqrtf(fmaxf(2.f - 2.f * t3, 0.f))
              + sqrtf(fmaxf(2.f - 2.f * t4, 0.f));
    lr[row] = logf(sum * (1.f / KTOP) + 1e-8f);
}

// ---------------------------------------------------------------------------
// Kernel 4: out = -mean(logrho)
// ---------------------------------------------------------------------------
__global__ void kred(const float* __restrict__ lr, float* __restrict__ out) {
    int t = threadIdx.x;
    float s = 0.f;
    for (int i = t; i < N; i += 256) s += lr[i];
    #pragma unroll
    for (int o = 16; o; o >>= 1) s += __shfl_xor_sync(0xffffffffu, s, o);
    __shared__ float ws[8];
    if ((t & 31) == 0) ws[t >> 5] = s;
    __syncthreads();
    if (t == 0) {
        float tot = 0.f;
        #pragma unroll
        for (int i = 0; i < 8; i++) tot += ws[i];
        out[0] = -tot / (float)N;
    }
}

// ---------------------------------------------------------------------------
extern "C" void kernel_launch(void* const* d_in, const int* in_sizes, int n_in,
                              void* d_out, int out_size) {
    (void)in_sizes; (void)n_in; (void)out_size;
    const float* x = (const float*)d_in[0];
    float* out = (float*)d_out;

    __nv_bfloat16* xnb; cudaGetSymbolAddress((void**)&xnb, g_xnb);
    float* gpart;       cudaGetSymbolAddress((void**)&gpart, g_part);
    float* lrho;        cudaGetSymbolAddress((void**)&lrho, g_logrho);

    cudaFuncSetAttribute(gemm_topk, cudaFuncAttributeMaxDynamicSharedMemorySize, SMEM_TOTAL);

    knorm<<<N, 128>>>(x, xnb);
    gemm_topk<<<GRID, NTHREADS, SMEM_TOTAL>>>(xnb, gpart);
    kfinal<<<N / 256, 256>>>(gpart, lrho);
    kred<<<1, 256>>>(lrho, out);
}